// round 15
// baseline (speedup 1.0000x reference)
#include <cuda_runtime.h>
#include <cuda_fp16.h>

// SAM Vision Attention: B=1, H=W=64, N=4096, C=768, nh=12, hd=64
// R15: persistent flash with HALVED work granularity: 64-query items
//      (R8-validated 4-warp body), 3 CTAs/SM -> 456 slots stealing over
//      768 items. GEMMs unchanged (validated R13).

#define NH 12
#define NQ 4096
#define HD 64
#define CDIM 768
#define L2E 1.44269504f
#define SCALE_L2E (0.125f * 1.44269504f)   // 64^-0.5 * log2(e), folded into k

#define FLASH_ITEMS 768                    // (head, image-row) pairs
#define FLASH_GRID 456                     // 152 SMs x 3 CTAs

__device__ __half g_q16[NH * NQ * HD];
__device__ __half g_k16[NH * NQ * HD];        // pre-scaled by SCALE_L2E
__device__ __half g_v16[NH * NQ * HD];
__device__ __half g_ao16[NQ * CDIM];          // attention output (proj A input)
__device__ __half g_x16[NQ * CDIM];           // x in fp16
__device__ __half g_wqkvT[3 * CDIM * CDIM];   // qkv_w^T  [2304][768] fp16
__device__ __half g_wprojT[CDIM * CDIM];      // proj_w^T [768][768] fp16
__device__ int    g_counter;                  // flash work-stealing counter

// ---------------------------------------------------------------------------
// helpers
// ---------------------------------------------------------------------------
__device__ __forceinline__ void mma16816(float* c, const unsigned* a,
                                         unsigned b0, unsigned b1) {
    asm volatile(
        "mma.sync.aligned.m16n8k16.row.col.f32.f16.f16.f32 "
        "{%0,%1,%2,%3}, {%4,%5,%6,%7}, {%8,%9}, {%0,%1,%2,%3};\n"
        : "+f"(c[0]), "+f"(c[1]), "+f"(c[2]), "+f"(c[3])
        : "r"(a[0]), "r"(a[1]), "r"(a[2]), "r"(a[3]), "r"(b0), "r"(b1));
}

__device__ __forceinline__ unsigned f2h2(float x, float y) {
    __half2 h = __floats2half2_rn(x, y);
    return *(unsigned*)&h;
}

__device__ __forceinline__ float ex2f(float x) {
    float y;
    asm("ex2.approx.f32 %0, %1;" : "=f"(y) : "f"(x));
    return y;
}

__device__ __forceinline__ void cp_async16(void* dst, const void* src) {
    unsigned d = (unsigned)__cvta_generic_to_shared(dst);
    asm volatile("cp.async.cg.shared.global [%0], [%1], 16;\n" :: "r"(d), "l"(src));
}
#define CP_COMMIT asm volatile("cp.async.commit_group;\n")
#define CP_WAIT(n) asm volatile("cp.async.wait_group %0;\n" :: "n"(n))

__device__ __forceinline__ void ldsm4(unsigned& r0, unsigned& r1, unsigned& r2,
                                      unsigned& r3, unsigned a) {
    asm volatile("ldmatrix.sync.aligned.m8n8.x4.shared.b16 {%0,%1,%2,%3}, [%4];"
                 : "=r"(r0), "=r"(r1), "=r"(r2), "=r"(r3) : "r"(a));
}
__device__ __forceinline__ void ldsm4t(unsigned& r0, unsigned& r1, unsigned& r2,
                                       unsigned& r3, unsigned a) {
    asm volatile("ldmatrix.sync.aligned.m8n8.x4.trans.shared.b16 {%0,%1,%2,%3}, [%4];"
                 : "=r"(r0), "=r"(r1), "=r"(r2), "=r"(r3) : "r"(a));
}

// ---------------------------------------------------------------------------
// one-time conversion kernels (globals referenced from device code only)
// ---------------------------------------------------------------------------
__global__ void conv_x_kernel(const float* __restrict__ X) {
    int i = blockIdx.x * 256 + threadIdx.x;
    if (i == 0) g_counter = 0;                 // reset flash work counter
    if (i < NQ * CDIM / 4) {
        float4 v = ((const float4*)X)[i];
        __half2* o = (__half2*)(g_x16 + i * 4);
        o[0] = __floats2half2_rn(v.x, v.y);
        o[1] = __floats2half2_rn(v.z, v.w);
    }
}

__global__ void transpose_qkv_kernel(const float* __restrict__ W) {
    __shared__ float tile[32][33];
    int bn = blockIdx.x * 32, bk = blockIdx.y * 32;
    int tx = threadIdx.x, ty = threadIdx.y;
#pragma unroll
    for (int i = 0; i < 32; i += 8)
        tile[ty + i][tx] = W[(size_t)(bk + ty + i) * 2304 + bn + tx];
    __syncthreads();
#pragma unroll
    for (int i = 0; i < 32; i += 8)
        g_wqkvT[(size_t)(bn + ty + i) * 768 + bk + tx] = __float2half(tile[tx][ty + i]);
}

__global__ void transpose_proj_kernel(const float* __restrict__ W) {
    __shared__ float tile[32][33];
    int bn = blockIdx.x * 32, bk = blockIdx.y * 32;
    int tx = threadIdx.x, ty = threadIdx.y;
#pragma unroll
    for (int i = 0; i < 32; i += 8)
        tile[ty + i][tx] = W[(size_t)(bk + ty + i) * 768 + bn + tx];
    __syncthreads();
#pragma unroll
    for (int i = 0; i < 32; i += 8)
        g_wprojT[(size_t)(bn + ty + i) * 768 + bk + tx] = __float2half(tile[tx][ty + i]);
}

// ---------------------------------------------------------------------------
// Shared fp16 HMMA GEMM body (validated R13): BM=BN=128, BK=64, 8 warps,
// 2-stage cp.async, single-sync schedule. Pitch 72 halves (144 B).
// ---------------------------------------------------------------------------
struct GAcc { float c[2][8][4]; };

__device__ __forceinline__ void gemm_load_tile64(const __half* __restrict__ A,
                                                 const __half* __restrict__ BT,
                                                 int bm, int bn, int k0,
                                                 __half* dA, __half* dB, int tid) {
#pragma unroll
    for (int i = 0; i < 4; i++) {
        int cdx = tid + i * 256;
        int row = cdx >> 3, off = (cdx & 7) * 8;
        cp_async16(dA + row * 72 + off, A + (size_t)(bm + row) * 768 + k0 + off);
        cp_async16(dB + row * 72 + off, BT + (size_t)(bn + row) * 768 + k0 + off);
    }
    CP_COMMIT;
}

__device__ __forceinline__ void hgemm_body(const __half* __restrict__ A,
                                           const __half* __restrict__ BT,
                                           int bm, int bn, __half* As, __half* Bs,
                                           GAcc& F) {
    const int tid = threadIdx.x;
    const int w = tid >> 5, lane = tid & 31;
    const int m0 = (w >> 1) * 32, n0 = (w & 1) * 64;
    const int mat = lane >> 3, mr = lane & 7;

    const unsigned aconst = ((mat & 1) * 8 + mr) * 144 + (mat >> 1) * 16;
    const unsigned bconst = ((mat >> 1) * 8 + mr) * 144 + (mat & 1) * 16;
    const unsigned abase = (unsigned)__cvta_generic_to_shared(As) + m0 * 144 + aconst;
    const unsigned bbase = (unsigned)__cvta_generic_to_shared(Bs) + n0 * 144 + bconst;

#pragma unroll
    for (int mi = 0; mi < 2; mi++)
#pragma unroll
        for (int nj = 0; nj < 8; nj++)
#pragma unroll
            for (int e = 0; e < 4; e++) F.c[mi][nj][e] = 0.f;

    gemm_load_tile64(A, BT, bm, bn, 0, As, Bs, tid);

    for (int kt = 0; kt < 12; kt++) {
        const int cur = kt & 1;
        CP_WAIT(0);
        __syncthreads();

        if (kt < 11)
            gemm_load_tile64(A, BT, bm, bn, (kt + 1) * 64,
                             As + (cur ^ 1) * 9216, Bs + (cur ^ 1) * 9216, tid);

        const unsigned ab = abase + cur * 18432;
        const unsigned bb = bbase + cur * 18432;
#pragma unroll
        for (int ks = 0; ks < 4; ks++) {
            unsigned a[2][4], b[8][2];
#pragma unroll
            for (int mi = 0; mi < 2; mi++)
                ldsm4(a[mi][0], a[mi][1], a[mi][2], a[mi][3],
                      ab + mi * (16 * 144) + ks * 32);
#pragma unroll
            for (int nj2 = 0; nj2 < 4; nj2++)
                ldsm4(b[2 * nj2][0], b[2 * nj2][1], b[2 * nj2 + 1][0], b[2 * nj2 + 1][1],
                      bb + nj2 * (16 * 144) + ks * 32);
#pragma unroll
            for (int mi = 0; mi < 2; mi++)
#pragma unroll
                for (int nj = 0; nj < 8; nj++)
                    mma16816(F.c[mi][nj], a[mi], b[nj][0], b[nj][1]);
        }
    }
    __syncthreads();
}

// ---------------------------------------------------------------------------
// QKV GEMM: M=4096, N=2304 (validated R13)
// ---------------------------------------------------------------------------
__global__ __launch_bounds__(256, 2) void qkv_hgemm16(const float* __restrict__ bias) {
    extern __shared__ __half smq[];
    const int bm = blockIdx.y * 128, bn = blockIdx.x * 128;
    const int tid = threadIdx.x;
    const int w = tid >> 5, lane = tid & 31;
    const int g = lane >> 2, t = lane & 3;
    const int m0 = (w >> 1) * 32, n0 = (w & 1) * 64;

    GAcc F;
    hgemm_body(g_x16, g_wqkvT, bm, bn, smq, smq + 18432, F);

#pragma unroll
    for (int mi = 0; mi < 2; mi++)
#pragma unroll
        for (int nj = 0; nj < 8; nj++)
#pragma unroll
            for (int e2 = 0; e2 < 2; e2++) {
                int row = bm + m0 + mi * 16 + g + e2 * 8;
                int col = bn + n0 + nj * 8 + 2 * t;
                float v0 = F.c[mi][nj][e2 * 2 + 0] + bias[col];
                float v1 = F.c[mi][nj][e2 * 2 + 1] + bias[col + 1];
                int which = col / 768;
                int rem = col - which * 768;
                int head = rem >> 6, d = rem & 63;
                size_t off = ((size_t)head * NQ + row) * HD + d;
                if (which == 0)
                    *(__half2*)(g_q16 + off) = __floats2half2_rn(v0, v1);
                else if (which == 1)
                    *(__half2*)(g_k16 + off) =
                        __floats2half2_rn(v0 * SCALE_L2E, v1 * SCALE_L2E);
                else
                    *(__half2*)(g_v16 + off) = __floats2half2_rn(v0, v1);
            }
}

// ---------------------------------------------------------------------------
// proj GEMM: M=4096, N=768 (validated R13)
// ---------------------------------------------------------------------------
__global__ __launch_bounds__(256, 2) void proj_hgemm16(const float* __restrict__ bias,
                                                       float* __restrict__ out) {
    extern __shared__ __half smp[];
    const int bm = blockIdx.y * 128, bn = blockIdx.x * 128;
    const int tid = threadIdx.x;
    const int w = tid >> 5, lane = tid & 31;
    const int g = lane >> 2, t = lane & 3;
    const int m0 = (w >> 1) * 32, n0 = (w & 1) * 64;

    GAcc F;
    hgemm_body(g_ao16, g_wprojT, bm, bn, smp, smp + 18432, F);

#pragma unroll
    for (int mi = 0; mi < 2; mi++)
#pragma unroll
        for (int nj = 0; nj < 8; nj++)
#pragma unroll
            for (int e2 = 0; e2 < 2; e2++) {
                int row = bm + m0 + mi * 16 + g + e2 * 8;
                int col = bn + n0 + nj * 8 + 2 * t;
                float2 v;
                v.x = F.c[mi][nj][e2 * 2 + 0] + bias[col];
                v.y = F.c[mi][nj][e2 * 2 + 1] + bias[col + 1];
                *(float2*)&out[(size_t)row * 768 + col] = v;
            }
}

// ---------------------------------------------------------------------------
// Persistent flash attention: 456 CTAs (3/SM), stealing over 768 items.
// Per item: 64 queries (one image row qh) of one head. Body = validated R8:
// 4 warps x 16 rows, fused rel-bias prologue, 2-stage K/V ring, base-2 softmax.
// smem (halves): Qs[0,4608) | K 2x[4608,13824) | V 2x[13824,23040)
//                RWs[23040,27648) | RHs[27648,32256)    = 64512 B
// prologue aliases: Bh[64][72]@4608, Bw[128][72]@9216, P[64][136]@4608
// ---------------------------------------------------------------------------
__global__ __launch_bounds__(128, 3) void flash_attn(const float* __restrict__ rph,
                                                     const float* __restrict__ rpw) {
    extern __shared__ __half smd[];
    __shared__ int s_item;
    __half* Qs  = smd;                 // [64][72]
    __half* Ksh = smd + 4608;          // 2 x [64][72]
    __half* Vsh = smd + 13824;         // 2 x [64][72]
    __half* RWs = smd + 23040;         // [64][72]  (xL2E)
    __half* RHs = smd + 27648;         // [64][72]  (xL2E)

    const int tid  = threadIdx.x;
    const int w    = tid >> 5;         // 0..3
    const int lane = tid & 31;
    const int g    = lane >> 2;
    const int t    = lane & 3;
    const int r0 = 16 * w + g;         // 0..63
    const int r1 = r0 + 8;

    const int mat = lane >> 3, mr = lane & 7;
    const unsigned smem_u32 = (unsigned)__cvta_generic_to_shared(smd);
    const unsigned kconst = ((mat >> 1) * 8 + mr) * 144 + (mat & 1) * 16;
    const unsigned vconst = ((mat & 1) * 8 + mr) * 144 + (mat >> 1) * 16;
    const unsigned kbase0 = smem_u32 + 4608 * 2 + kconst;
    const unsigned vbase0 = smem_u32 + 13824 * 2 + vconst;

    while (true) {
        if (tid == 0) s_item = atomicAdd(&g_counter, 1);
        __syncthreads();
        const int item = s_item;
        if (item >= FLASH_ITEMS) return;
        const int head = item >> 6;        // item / 64
        const int qh   = item & 63;        // item % 64

        const size_t qbase = ((size_t)head * NQ + qh * 64) * HD;
        const size_t hbase = (size_t)head * NQ * HD;

        // ---- prologue phase 1: load Q, Bh, Bw ----
        {
            __half* Bh = smd + 4608;       // [64][72]
            __half* Bw = smd + 9216;       // [128][72], row 127 = 0
            const unsigned* gq = (const unsigned*)(g_q16 + qbase);
            for (int i = tid; i < 2048; i += 128) {
                int r = i >> 5, c2 = i & 31;
                *(unsigned*)&Qs[r * 72 + c2 * 2] = gq[i];
            }
            for (int i = tid; i < 4096; i += 128) {
                int kh = i >> 6, c = i & 63;
                Bh[kh * 72 + c] = __float2half(rph[(qh - kh + 63) * 64 + c]);
            }
            for (int i = tid; i < 127 * 64; i += 128) {
                int r = i >> 6, c = i & 63;
                Bw[r * 72 + c] = __float2half(rpw[i]);
            }
            if (tid < 64) Bw[127 * 72 + tid] = __float2half(0.f);
        }
        __syncthreads();

        // ---- Q fragments ----
        unsigned qa[4][4];
#pragma unroll
        for (int u = 0; u < 4; u++) {
            int d = 16 * u + 2 * t;
            qa[u][0] = *(const unsigned*)&Qs[r0 * 72 + d];
            qa[u][1] = *(const unsigned*)&Qs[r1 * 72 + d];
            qa[u][2] = *(const unsigned*)&Qs[r0 * 72 + d + 8];
            qa[u][3] = *(const unsigned*)&Qs[r1 * 72 + d + 8];
        }

        // ---- prologue phase 2: RH = Q @ Bh^T (xL2E) ----
        {
            float ch[8][4];
#pragma unroll
            for (int j = 0; j < 8; j++)
#pragma unroll
                for (int e = 0; e < 4; e++) ch[j][e] = 0.f;
            const unsigned bhb = smem_u32 + 4608 * 2 + kconst;
#pragma unroll
            for (int u = 0; u < 4; u++)
#pragma unroll
                for (int j2 = 0; j2 < 4; j2++) {
                    unsigned b0, b1, b2, b3;
                    ldsm4(b0, b1, b2, b3, bhb + j2 * 2304 + u * 32);
                    mma16816(ch[2 * j2],     qa[u], b0, b1);
                    mma16816(ch[2 * j2 + 1], qa[u], b2, b3);
                }
#pragma unroll
            for (int j = 0; j < 8; j++) {
                int col = 8 * j + 2 * t;
                *(unsigned*)&RHs[r0 * 72 + col] = f2h2(ch[j][0] * L2E, ch[j][1] * L2E);
                *(unsigned*)&RHs[r1 * 72 + col] = f2h2(ch[j][2] * L2E, ch[j][3] * L2E);
            }
        }

        // ---- prologue phase 3: P = Q @ Bw^T, gather RWs[q][kw] = P[q][q-kw+63] ----
        {
            float cp[16][4];
#pragma unroll
            for (int j = 0; j < 16; j++)
#pragma unroll
                for (int e = 0; e < 4; e++) cp[j][e] = 0.f;
            const unsigned bwb = smem_u32 + 9216 * 2 + kconst;
#pragma unroll
            for (int u = 0; u < 4; u++)
#pragma unroll
                for (int j2 = 0; j2 < 8; j2++) {
                    unsigned b0, b1, b2, b3;
                    ldsm4(b0, b1, b2, b3, bwb + j2 * 2304 + u * 32);
                    mma16816(cp[2 * j2],     qa[u], b0, b1);
                    mma16816(cp[2 * j2 + 1], qa[u], b2, b3);
                }
            __syncthreads();   // ldsm reads of Bh/Bw done before overwrite

            __half* Psm = smd + 4608;      // [64][136]
#pragma unroll
            for (int nj = 0; nj < 16; nj++) {
                int col = 8 * nj + 2 * t;
                *(unsigned*)&Psm[r0 * 136 + col] = f2h2(cp[nj][0] * L2E, cp[nj][1] * L2E);
                *(unsigned*)&Psm[r1 * 136 + col] = f2h2(cp[nj][2] * L2E, cp[nj][3] * L2E);
            }
            __syncthreads();

            for (int i = tid; i < 4096; i += 128) {
                int q = i >> 6, kw = i & 63;
                RWs[q * 72 + kw] = Psm[q * 136 + (q - kw + 63)];
            }
        }
        __syncthreads();       // gather done before K/V prefetch overwrites

        // ---- prefetch key tile 0 ----
        {
            const __half* gk = g_k16 + hbase;
            const __half* gv = g_v16 + hbase;
#pragma unroll
            for (int i = 0; i < 4; i++) {
                int c = tid + i * 128;
                int key = c >> 3, off = (c & 7) * 8;
                cp_async16(&Ksh[key * 72 + off], gk + c * 8);
                cp_async16(&Vsh[key * 72 + off], gv + c * 8);
            }
            CP_COMMIT;
        }

        float o[8][4];
#pragma unroll
        for (int j = 0; j < 8; j++)
#pragma unroll
            for (int e = 0; e < 4; e++) o[j][e] = 0.f;
        float m0 = -1e30f, m1 = -1e30f, l0 = 0.f, l1 = 0.f;

        for (int kt = 0; kt < 64; kt++) {
            const int cur = kt & 1;
            if (kt < 63) {
                const __half* gk = g_k16 + hbase + (size_t)(kt + 1) * 4096;
                const __half* gv = g_v16 + hbase + (size_t)(kt + 1) * 4096;
                __half* dk = Ksh + (cur ^ 1) * 4608;
                __half* dv = Vsh + (cur ^ 1) * 4608;
#pragma unroll
                for (int i = 0; i < 4; i++) {
                    int c = tid + i * 128;
                    int key = c >> 3, off = (c & 7) * 8;
                    cp_async16(&dk[key * 72 + off], gk + c * 8);
                    cp_async16(&dv[key * 72 + off], gv + c * 8);
                }
                CP_COMMIT;
                CP_WAIT(1);
            } else {
                CP_WAIT(0);
            }
            __syncthreads();

            // ---- S = Q @ K^T ----
            float c[8][4];
#pragma unroll
            for (int j = 0; j < 8; j++)
#pragma unroll
                for (int e = 0; e < 4; e++) c[j][e] = 0.f;
            {
                const unsigned kb = kbase0 + cur * 9216;
#pragma unroll
                for (int u = 0; u < 4; u++) {
#pragma unroll
                    for (int j2 = 0; j2 < 4; j2++) {
                        unsigned b0, b1, b2, b3;
                        ldsm4(b0, b1, b2, b3, kb + j2 * 2304 + u * 32);
                        mma16816(c[2 * j2],     qa[u], b0, b1);
                        mma16816(c[2 * j2 + 1], qa[u], b2, b3);
                    }
                }
            }

            // ---- bias (xL2E) ----
            float rh0 = __half2float(RHs[r0 * 72 + kt]);
            float rh1 = __half2float(RHs[r1 * 72 + kt]);
#pragma unroll
            for (int j = 0; j < 8; j++) {
                int col = 8 * j + 2 * t;
                float2 w0 = __half22float2(*(const __half2*)&RWs[r0 * 72 + col]);
                float2 w1 = __half22float2(*(const __half2*)&RWs[r1 * 72 + col]);
                c[j][0] += rh0 + w0.x;
                c[j][1] += rh0 + w0.y;
                c[j][2] += rh1 + w1.x;
                c[j][3] += rh1 + w1.y;
            }

            // ---- online softmax (base-2) ----
            float mx0 = -1e30f, mx1 = -1e30f;
#pragma unroll
            for (int j = 0; j < 8; j++) {
                mx0 = fmaxf(mx0, fmaxf(c[j][0], c[j][1]));
                mx1 = fmaxf(mx1, fmaxf(c[j][2], c[j][3]));
            }
            mx0 = fmaxf(mx0, __shfl_xor_sync(0xffffffffu, mx0, 1));
            mx0 = fmaxf(mx0, __shfl_xor_sync(0xffffffffu, mx0, 2));
            mx1 = fmaxf(mx1, __shfl_xor_sync(0xffffffffu, mx1, 1));
            mx1 = fmaxf(mx1, __shfl_xor_sync(0xffffffffu, mx1, 2));

            float mn0 = fmaxf(m0, mx0), mn1 = fmaxf(m1, mx1);
            float al0 = ex2f(m0 - mn0), al1 = ex2f(m1 - mn1);
            m0 = mn0; m1 = mn1;

            float s0 = 0.f, s1 = 0.f;
#pragma unroll
            for (int j = 0; j < 8; j++) {
                c[j][0] = ex2f(c[j][0] - mn0); s0 += c[j][0];
                c[j][1] = ex2f(c[j][1] - mn0); s0 += c[j][1];
                c[j][2] = ex2f(c[j][2] - mn1); s1 += c[j][2];
                c[j][3] = ex2f(c[j][3] - mn1); s1 += c[j][3];
            }
            s0 += __shfl_xor_sync(0xffffffffu, s0, 1);
            s0 += __shfl_xor_sync(0xffffffffu, s0, 2);
            s1 += __shfl_xor_sync(0xffffffffu, s1, 1);
            s1 += __shfl_xor_sync(0xffffffffu, s1, 2);
            l0 = l0 * al0 + s0;
            l1 = l1 * al1 + s1;

#pragma unroll
            for (int j = 0; j < 8; j++) {
                o[j][0] *= al0; o[j][1] *= al0;
                o[j][2] *= al1; o[j][3] *= al1;
            }

            // ---- O += P @ V ----
            {
                const unsigned vb = vbase0 + cur * 9216;
#pragma unroll
                for (int u = 0; u < 4; u++) {
                    unsigned pa[4];
                    pa[0] = f2h2(c[2 * u][0], c[2 * u][1]);
                    pa[1] = f2h2(c[2 * u][2], c[2 * u][3]);
                    pa[2] = f2h2(c[2 * u + 1][0], c[2 * u + 1][1]);
                    pa[3] = f2h2(c[2 * u + 1][2], c[2 * u + 1][3]);
#pragma unroll
                    for (int j2 = 0; j2 < 4; j2++) {
                        unsigned b0, b1, b2, b3;
                        ldsm4t(b0, b1, b2, b3, vb + u * 2304 + j2 * 32);
                        mma16816(o[2 * j2],     pa, b0, b1);
                        mma16816(o[2 * j2 + 1], pa, b2, b3);
                    }
                }
            }
            __syncthreads();
        }

        float inv0 = 1.f / l0, inv1 = 1.f / l1;
        __half* outp = g_ao16 + (size_t)(qh * 64) * CDIM + head * 64;
#pragma unroll
        for (int j = 0; j < 8; j++) {
            int col = 8 * j + 2 * t;
            *(__half2*)&outp[(size_t)r0 * CDIM + col] =
                __floats2half2_rn(o[j][0] * inv0, o[j][1] * inv0);
            *(__half2*)&outp[(size_t)r1 * CDIM + col] =
                __floats2half2_rn(o[j][2] * inv1, o[j][3] * inv1);
        }
        __syncthreads();   // smem quiesced before next item's prologue
    }
}

// ---------------------------------------------------------------------------
extern "C" void kernel_launch(void* const* d_in, const int* in_sizes, int n_in,
                              void* d_out, int out_size) {
    const float* x      = (const float*)d_in[0];
    const float* qkv_w  = (const float*)d_in[1];
    const float* qkv_b  = (const float*)d_in[2];
    const float* proj_w = (const float*)d_in[3];
    const float* proj_b = (const float*)d_in[4];
    const float* rph    = (const float*)d_in[5];
    const float* rpw    = (const float*)d_in[6];
    float* out = (float*)d_out;

    const int GEMM_SMEM  = 36864 * 2;   // 73728 B
    const int FLASH_SMEM = 32256 * 2;   // 64512 B -> 3 CTAs/SM
    cudaFuncSetAttribute(qkv_hgemm16, cudaFuncAttributeMaxDynamicSharedMemorySize, GEMM_SMEM);
    cudaFuncSetAttribute(proj_hgemm16, cudaFuncAttributeMaxDynamicSharedMemorySize, GEMM_SMEM);
    cudaFuncSetAttribute(flash_attn, cudaFuncAttributeMaxDynamicSharedMemorySize, FLASH_SMEM);

    conv_x_kernel<<<(NQ * CDIM / 4 + 255) / 256, 256>>>(x);
    transpose_qkv_kernel<<<dim3(72, 24), dim3(32, 8)>>>(qkv_w);
    transpose_proj_kernel<<<dim3(24, 24), dim3(32, 8)>>>(proj_w);
    qkv_hgemm16<<<dim3(18, 32), 256, GEMM_SMEM>>>(qkv_b);
    flash_attn<<<FLASH_GRID, 128, FLASH_SMEM>>>(rph, rpw);
    proj_hgemm16<<<dim3(6, 32), 256, GEMM_SMEM>>>(proj_b, out);
}

// round 16
// speedup vs baseline: 1.0295x; 1.0295x over previous
#include <cuda_runtime.h>
#include <cuda_fp16.h>

// SAM Vision Attention: B=1, H=W=64, N=4096, C=768, nh=12, hd=64
// R16: flash inner loop -> single-sync schedule (wait0->sync->prefetch->
//      compute, as validated in the R13 GEMMs) + bias-initialized S
//      accumulators (deletes the bias add pass). conv_x + transposes fused
//      into one prep kernel. GEMMs unchanged (validated R13).

#define NH 12
#define NQ 4096
#define HD 64
#define CDIM 768
#define L2E 1.44269504f
#define SCALE_L2E (0.125f * 1.44269504f)   // 64^-0.5 * log2(e), folded into k

#define FLASH_ITEMS 768                    // (head, image-row) pairs
#define FLASH_GRID 456                     // 152 SMs x 3 CTAs

__device__ __half g_q16[NH * NQ * HD];
__device__ __half g_k16[NH * NQ * HD];        // pre-scaled by SCALE_L2E
__device__ __half g_v16[NH * NQ * HD];
__device__ __half g_ao16[NQ * CDIM];          // attention output (proj A input)
__device__ __half g_x16[NQ * CDIM];           // x in fp16
__device__ __half g_wqkvT[3 * CDIM * CDIM];   // qkv_w^T  [2304][768] fp16
__device__ __half g_wprojT[CDIM * CDIM];      // proj_w^T [768][768] fp16
__device__ int    g_counter;                  // flash work-stealing counter

// ---------------------------------------------------------------------------
// helpers
// ---------------------------------------------------------------------------
__device__ __forceinline__ void mma16816(float* c, const unsigned* a,
                                         unsigned b0, unsigned b1) {
    asm volatile(
        "mma.sync.aligned.m16n8k16.row.col.f32.f16.f16.f32 "
        "{%0,%1,%2,%3}, {%4,%5,%6,%7}, {%8,%9}, {%0,%1,%2,%3};\n"
        : "+f"(c[0]), "+f"(c[1]), "+f"(c[2]), "+f"(c[3])
        : "r"(a[0]), "r"(a[1]), "r"(a[2]), "r"(a[3]), "r"(b0), "r"(b1));
}

__device__ __forceinline__ unsigned f2h2(float x, float y) {
    __half2 h = __floats2half2_rn(x, y);
    return *(unsigned*)&h;
}

__device__ __forceinline__ float ex2f(float x) {
    float y;
    asm("ex2.approx.f32 %0, %1;" : "=f"(y) : "f"(x));
    return y;
}

__device__ __forceinline__ void cp_async16(void* dst, const void* src) {
    unsigned d = (unsigned)__cvta_generic_to_shared(dst);
    asm volatile("cp.async.cg.shared.global [%0], [%1], 16;\n" :: "r"(d), "l"(src));
}
#define CP_COMMIT asm volatile("cp.async.commit_group;\n")
#define CP_WAIT(n) asm volatile("cp.async.wait_group %0;\n" :: "n"(n))

__device__ __forceinline__ void ldsm4(unsigned& r0, unsigned& r1, unsigned& r2,
                                      unsigned& r3, unsigned a) {
    asm volatile("ldmatrix.sync.aligned.m8n8.x4.shared.b16 {%0,%1,%2,%3}, [%4];"
                 : "=r"(r0), "=r"(r1), "=r"(r2), "=r"(r3) : "r"(a));
}
__device__ __forceinline__ void ldsm4t(unsigned& r0, unsigned& r1, unsigned& r2,
                                       unsigned& r3, unsigned a) {
    asm volatile("ldmatrix.sync.aligned.m8n8.x4.trans.shared.b16 {%0,%1,%2,%3}, [%4];"
                 : "=r"(r0), "=r"(r1), "=r"(r2), "=r"(r3) : "r"(a));
}

// ---------------------------------------------------------------------------
// fused prep kernel: conv x -> fp16, transpose qkv_w and proj_w to fp16,
// reset flash work counter. 5376 blocks x 256 threads:
//   [0,3072)    conv_x  (one float4 per thread)
//   [3072,4800) qkv_w transpose  (72 x 24 tiles of 32x32)
//   [4800,5376) proj_w transpose (24 x 24 tiles)
// ---------------------------------------------------------------------------
__global__ void prep_kernel(const float* __restrict__ X,
                            const float* __restrict__ Wqkv,
                            const float* __restrict__ Wproj) {
    __shared__ float tile[32][33];
    const int bid = blockIdx.x;
    const int tid = threadIdx.x;
    if (bid == 0 && tid == 0) g_counter = 0;

    if (bid < 3072) {
        int i = bid * 256 + tid;
        float4 v = ((const float4*)X)[i];
        __half2* o = (__half2*)(g_x16 + (size_t)i * 4);
        o[0] = __floats2half2_rn(v.x, v.y);
        o[1] = __floats2half2_rn(v.z, v.w);
    } else if (bid < 4800) {
        int b = bid - 3072;
        int bn = (b % 72) * 32, bk = (b / 72) * 32;
        int tx = tid & 31, ty = tid >> 5;      // 32 x 8
#pragma unroll
        for (int i = 0; i < 32; i += 8)
            tile[ty + i][tx] = Wqkv[(size_t)(bk + ty + i) * 2304 + bn + tx];
        __syncthreads();
#pragma unroll
        for (int i = 0; i < 32; i += 8)
            g_wqkvT[(size_t)(bn + ty + i) * 768 + bk + tx] =
                __float2half(tile[tx][ty + i]);
    } else {
        int b = bid - 4800;
        int bn = (b % 24) * 32, bk = (b / 24) * 32;
        int tx = tid & 31, ty = tid >> 5;
#pragma unroll
        for (int i = 0; i < 32; i += 8)
            tile[ty + i][tx] = Wproj[(size_t)(bk + ty + i) * 768 + bn + tx];
        __syncthreads();
#pragma unroll
        for (int i = 0; i < 32; i += 8)
            g_wprojT[(size_t)(bn + ty + i) * 768 + bk + tx] =
                __float2half(tile[tx][ty + i]);
    }
}

// ---------------------------------------------------------------------------
// Shared fp16 HMMA GEMM body (validated R13): BM=BN=128, BK=64, 8 warps,
// 2-stage cp.async, single-sync schedule. Pitch 72 halves (144 B).
// ---------------------------------------------------------------------------
struct GAcc { float c[2][8][4]; };

__device__ __forceinline__ void gemm_load_tile64(const __half* __restrict__ A,
                                                 const __half* __restrict__ BT,
                                                 int bm, int bn, int k0,
                                                 __half* dA, __half* dB, int tid) {
#pragma unroll
    for (int i = 0; i < 4; i++) {
        int cdx = tid + i * 256;
        int row = cdx >> 3, off = (cdx & 7) * 8;
        cp_async16(dA + row * 72 + off, A + (size_t)(bm + row) * 768 + k0 + off);
        cp_async16(dB + row * 72 + off, BT + (size_t)(bn + row) * 768 + k0 + off);
    }
    CP_COMMIT;
}

__device__ __forceinline__ void hgemm_body(const __half* __restrict__ A,
                                           const __half* __restrict__ BT,
                                           int bm, int bn, __half* As, __half* Bs,
                                           GAcc& F) {
    const int tid = threadIdx.x;
    const int w = tid >> 5, lane = tid & 31;
    const int m0 = (w >> 1) * 32, n0 = (w & 1) * 64;
    const int mat = lane >> 3, mr = lane & 7;

    const unsigned aconst = ((mat & 1) * 8 + mr) * 144 + (mat >> 1) * 16;
    const unsigned bconst = ((mat >> 1) * 8 + mr) * 144 + (mat & 1) * 16;
    const unsigned abase = (unsigned)__cvta_generic_to_shared(As) + m0 * 144 + aconst;
    const unsigned bbase = (unsigned)__cvta_generic_to_shared(Bs) + n0 * 144 + bconst;

#pragma unroll
    for (int mi = 0; mi < 2; mi++)
#pragma unroll
        for (int nj = 0; nj < 8; nj++)
#pragma unroll
            for (int e = 0; e < 4; e++) F.c[mi][nj][e] = 0.f;

    gemm_load_tile64(A, BT, bm, bn, 0, As, Bs, tid);

    for (int kt = 0; kt < 12; kt++) {
        const int cur = kt & 1;
        CP_WAIT(0);
        __syncthreads();

        if (kt < 11)
            gemm_load_tile64(A, BT, bm, bn, (kt + 1) * 64,
                             As + (cur ^ 1) * 9216, Bs + (cur ^ 1) * 9216, tid);

        const unsigned ab = abase + cur * 18432;
        const unsigned bb = bbase + cur * 18432;
#pragma unroll
        for (int ks = 0; ks < 4; ks++) {
            unsigned a[2][4], b[8][2];
#pragma unroll
            for (int mi = 0; mi < 2; mi++)
                ldsm4(a[mi][0], a[mi][1], a[mi][2], a[mi][3],
                      ab + mi * (16 * 144) + ks * 32);
#pragma unroll
            for (int nj2 = 0; nj2 < 4; nj2++)
                ldsm4(b[2 * nj2][0], b[2 * nj2][1], b[2 * nj2 + 1][0], b[2 * nj2 + 1][1],
                      bb + nj2 * (16 * 144) + ks * 32);
#pragma unroll
            for (int mi = 0; mi < 2; mi++)
#pragma unroll
                for (int nj = 0; nj < 8; nj++)
                    mma16816(F.c[mi][nj], a[mi], b[nj][0], b[nj][1]);
        }
    }
    __syncthreads();
}

// ---------------------------------------------------------------------------
// QKV GEMM: M=4096, N=2304 (validated R13)
// ---------------------------------------------------------------------------
__global__ __launch_bounds__(256, 2) void qkv_hgemm16(const float* __restrict__ bias) {
    extern __shared__ __half smq[];
    const int bm = blockIdx.y * 128, bn = blockIdx.x * 128;
    const int tid = threadIdx.x;
    const int w = tid >> 5, lane = tid & 31;
    const int g = lane >> 2, t = lane & 3;
    const int m0 = (w >> 1) * 32, n0 = (w & 1) * 64;

    GAcc F;
    hgemm_body(g_x16, g_wqkvT, bm, bn, smq, smq + 18432, F);

#pragma unroll
    for (int mi = 0; mi < 2; mi++)
#pragma unroll
        for (int nj = 0; nj < 8; nj++)
#pragma unroll
            for (int e2 = 0; e2 < 2; e2++) {
                int row = bm + m0 + mi * 16 + g + e2 * 8;
                int col = bn + n0 + nj * 8 + 2 * t;
                float v0 = F.c[mi][nj][e2 * 2 + 0] + bias[col];
                float v1 = F.c[mi][nj][e2 * 2 + 1] + bias[col + 1];
                int which = col / 768;
                int rem = col - which * 768;
                int head = rem >> 6, d = rem & 63;
                size_t off = ((size_t)head * NQ + row) * HD + d;
                if (which == 0)
                    *(__half2*)(g_q16 + off) = __floats2half2_rn(v0, v1);
                else if (which == 1)
                    *(__half2*)(g_k16 + off) =
                        __floats2half2_rn(v0 * SCALE_L2E, v1 * SCALE_L2E);
                else
                    *(__half2*)(g_v16 + off) = __floats2half2_rn(v0, v1);
            }
}

// ---------------------------------------------------------------------------
// proj GEMM: M=4096, N=768 (validated R13)
// ---------------------------------------------------------------------------
__global__ __launch_bounds__(256, 2) void proj_hgemm16(const float* __restrict__ bias,
                                                       float* __restrict__ out) {
    extern __shared__ __half smp[];
    const int bm = blockIdx.y * 128, bn = blockIdx.x * 128;
    const int tid = threadIdx.x;
    const int w = tid >> 5, lane = tid & 31;
    const int g = lane >> 2, t = lane & 3;
    const int m0 = (w >> 1) * 32, n0 = (w & 1) * 64;

    GAcc F;
    hgemm_body(g_ao16, g_wprojT, bm, bn, smp, smp + 18432, F);

#pragma unroll
    for (int mi = 0; mi < 2; mi++)
#pragma unroll
        for (int nj = 0; nj < 8; nj++)
#pragma unroll
            for (int e2 = 0; e2 < 2; e2++) {
                int row = bm + m0 + mi * 16 + g + e2 * 8;
                int col = bn + n0 + nj * 8 + 2 * t;
                float2 v;
                v.x = F.c[mi][nj][e2 * 2 + 0] + bias[col];
                v.y = F.c[mi][nj][e2 * 2 + 1] + bias[col + 1];
                *(float2*)&out[(size_t)row * 768 + col] = v;
            }
}

// ---------------------------------------------------------------------------
// Persistent flash attention: 456 CTAs (3/SM), stealing over 768 items.
// Per item: 64 queries of one head. Single-sync K/V schedule; S accumulators
// initialized with the rel-pos bias (no separate add pass).
// smem (halves): Qs[0,4608) | K 2x[4608,13824) | V 2x[13824,23040)
//                RWs[23040,27648) | RHs[27648,32256)    = 64512 B
// ---------------------------------------------------------------------------
__global__ __launch_bounds__(128, 3) void flash_attn(const float* __restrict__ rph,
                                                     const float* __restrict__ rpw) {
    extern __shared__ __half smd[];
    __shared__ int s_item;
    __half* Qs  = smd;                 // [64][72]
    __half* Ksh = smd + 4608;          // 2 x [64][72]
    __half* Vsh = smd + 13824;         // 2 x [64][72]
    __half* RWs = smd + 23040;         // [64][72]  (xL2E)
    __half* RHs = smd + 27648;         // [64][72]  (xL2E)

    const int tid  = threadIdx.x;
    const int w    = tid >> 5;         // 0..3
    const int lane = tid & 31;
    const int g    = lane >> 2;
    const int t    = lane & 3;
    const int r0 = 16 * w + g;         // 0..63
    const int r1 = r0 + 8;

    const int mat = lane >> 3, mr = lane & 7;
    const unsigned smem_u32 = (unsigned)__cvta_generic_to_shared(smd);
    const unsigned kconst = ((mat >> 1) * 8 + mr) * 144 + (mat & 1) * 16;
    const unsigned vconst = ((mat & 1) * 8 + mr) * 144 + (mat >> 1) * 16;
    const unsigned kbase0 = smem_u32 + 4608 * 2 + kconst;
    const unsigned vbase0 = smem_u32 + 13824 * 2 + vconst;

    while (true) {
        if (tid == 0) s_item = atomicAdd(&g_counter, 1);
        __syncthreads();
        const int item = s_item;
        if (item >= FLASH_ITEMS) return;
        const int head = item >> 6;
        const int qh   = item & 63;

        const size_t qbase = ((size_t)head * NQ + qh * 64) * HD;
        const size_t hbase = (size_t)head * NQ * HD;

        // ---- prologue phase 1: load Q, Bh, Bw ----
        {
            __half* Bh = smd + 4608;       // [64][72]
            __half* Bw = smd + 9216;       // [128][72], row 127 = 0
            const unsigned* gq = (const unsigned*)(g_q16 + qbase);
            for (int i = tid; i < 2048; i += 128) {
                int r = i >> 5, c2 = i & 31;
                *(unsigned*)&Qs[r * 72 + c2 * 2] = gq[i];
            }
            for (int i = tid; i < 4096; i += 128) {
                int kh = i >> 6, c = i & 63;
                Bh[kh * 72 + c] = __float2half(rph[(qh - kh + 63) * 64 + c]);
            }
            for (int i = tid; i < 127 * 64; i += 128) {
                int r = i >> 6, c = i & 63;
                Bw[r * 72 + c] = __float2half(rpw[i]);
            }
            if (tid < 64) Bw[127 * 72 + tid] = __float2half(0.f);
        }
        __syncthreads();

        // ---- Q fragments ----
        unsigned qa[4][4];
#pragma unroll
        for (int u = 0; u < 4; u++) {
            int d = 16 * u + 2 * t;
            qa[u][0] = *(const unsigned*)&Qs[r0 * 72 + d];
            qa[u][1] = *(const unsigned*)&Qs[r1 * 72 + d];
            qa[u][2] = *(const unsigned*)&Qs[r0 * 72 + d + 8];
            qa[u][3] = *(const unsigned*)&Qs[r1 * 72 + d + 8];
        }

        // ---- prologue phase 2: RH = Q @ Bh^T (xL2E) ----
        {
            float ch[8][4];
#pragma unroll
            for (int j = 0; j < 8; j++)
#pragma unroll
                for (int e = 0; e < 4; e++) ch[j][e] = 0.f;
            const unsigned bhb = smem_u32 + 4608 * 2 + kconst;
#pragma unroll
            for (int u = 0; u < 4; u++)
#pragma unroll
                for (int j2 = 0; j2 < 4; j2++) {
                    unsigned b0, b1, b2, b3;
                    ldsm4(b0, b1, b2, b3, bhb + j2 * 2304 + u * 32);
                    mma16816(ch[2 * j2],     qa[u], b0, b1);
                    mma16816(ch[2 * j2 + 1], qa[u], b2, b3);
                }
#pragma unroll
            for (int j = 0; j < 8; j++) {
                int col = 8 * j + 2 * t;
                *(unsigned*)&RHs[r0 * 72 + col] = f2h2(ch[j][0] * L2E, ch[j][1] * L2E);
                *(unsigned*)&RHs[r1 * 72 + col] = f2h2(ch[j][2] * L2E, ch[j][3] * L2E);
            }
        }

        // ---- prologue phase 3: P = Q @ Bw^T, gather RWs[q][kw] = P[q][q-kw+63] ----
        {
            float cp[16][4];
#pragma unroll
            for (int j = 0; j < 16; j++)
#pragma unroll
                for (int e = 0; e < 4; e++) cp[j][e] = 0.f;
            const unsigned bwb = smem_u32 + 9216 * 2 + kconst;
#pragma unroll
            for (int u = 0; u < 4; u++)
#pragma unroll
                for (int j2 = 0; j2 < 8; j2++) {
                    unsigned b0, b1, b2, b3;
                    ldsm4(b0, b1, b2, b3, bwb + j2 * 2304 + u * 32);
                    mma16816(cp[2 * j2],     qa[u], b0, b1);
                    mma16816(cp[2 * j2 + 1], qa[u], b2, b3);
                }
            __syncthreads();

            __half* Psm = smd + 4608;      // [64][136]
#pragma unroll
            for (int nj = 0; nj < 16; nj++) {
                int col = 8 * nj + 2 * t;
                *(unsigned*)&Psm[r0 * 136 + col] = f2h2(cp[nj][0] * L2E, cp[nj][1] * L2E);
                *(unsigned*)&Psm[r1 * 136 + col] = f2h2(cp[nj][2] * L2E, cp[nj][3] * L2E);
            }
            __syncthreads();

            for (int i = tid; i < 4096; i += 128) {
                int q = i >> 6, kw = i & 63;
                RWs[q * 72 + kw] = Psm[q * 136 + (q - kw + 63)];
            }
        }
        __syncthreads();

        // ---- prefetch key tile 0 ----
        {
            const __half* gk = g_k16 + hbase;
            const __half* gv = g_v16 + hbase;
#pragma unroll
            for (int i = 0; i < 4; i++) {
                int c = tid + i * 128;
                int key = c >> 3, off = (c & 7) * 8;
                cp_async16(&Ksh[key * 72 + off], gk + c * 8);
                cp_async16(&Vsh[key * 72 + off], gv + c * 8);
            }
            CP_COMMIT;
        }

        float o[8][4];
#pragma unroll
        for (int j = 0; j < 8; j++)
#pragma unroll
            for (int e = 0; e < 4; e++) o[j][e] = 0.f;
        float m0 = -1e30f, m1 = -1e30f, l0 = 0.f, l1 = 0.f;

        for (int kt = 0; kt < 64; kt++) {
            const int cur = kt & 1;
            CP_WAIT(0);
            __syncthreads();   // tile kt visible; reads of buffer cur^1 done

            if (kt < 63) {
                const __half* gk = g_k16 + hbase + (size_t)(kt + 1) * 4096;
                const __half* gv = g_v16 + hbase + (size_t)(kt + 1) * 4096;
                __half* dk = Ksh + (cur ^ 1) * 4608;
                __half* dv = Vsh + (cur ^ 1) * 4608;
#pragma unroll
                for (int i = 0; i < 4; i++) {
                    int c = tid + i * 128;
                    int key = c >> 3, off = (c & 7) * 8;
                    cp_async16(&dk[key * 72 + off], gk + c * 8);
                    cp_async16(&dv[key * 72 + off], gv + c * 8);
                }
                CP_COMMIT;
            }

            // ---- S accumulators initialized with bias (rh + rw, xL2E) ----
            float c[8][4];
            {
                float rh0 = __half2float(RHs[r0 * 72 + kt]);
                float rh1 = __half2float(RHs[r1 * 72 + kt]);
#pragma unroll
                for (int j = 0; j < 8; j++) {
                    int col = 8 * j + 2 * t;
                    float2 w0 = __half22float2(*(const __half2*)&RWs[r0 * 72 + col]);
                    float2 w1 = __half22float2(*(const __half2*)&RWs[r1 * 72 + col]);
                    c[j][0] = rh0 + w0.x;
                    c[j][1] = rh0 + w0.y;
                    c[j][2] = rh1 + w1.x;
                    c[j][3] = rh1 + w1.y;
                }
            }

            // ---- S += Q @ K^T ----
            {
                const unsigned kb = kbase0 + cur * 9216;
#pragma unroll
                for (int u = 0; u < 4; u++) {
#pragma unroll
                    for (int j2 = 0; j2 < 4; j2++) {
                        unsigned b0, b1, b2, b3;
                        ldsm4(b0, b1, b2, b3, kb + j2 * 2304 + u * 32);
                        mma16816(c[2 * j2],     qa[u], b0, b1);
                        mma16816(c[2 * j2 + 1], qa[u], b2, b3);
                    }
                }
            }

            // ---- online softmax (base-2) ----
            float mx0 = -1e30f, mx1 = -1e30f;
#pragma unroll
            for (int j = 0; j < 8; j++) {
                mx0 = fmaxf(mx0, fmaxf(c[j][0], c[j][1]));
                mx1 = fmaxf(mx1, fmaxf(c[j][2], c[j][3]));
            }
            mx0 = fmaxf(mx0, __shfl_xor_sync(0xffffffffu, mx0, 1));
            mx0 = fmaxf(mx0, __shfl_xor_sync(0xffffffffu, mx0, 2));
            mx1 = fmaxf(mx1, __shfl_xor_sync(0xffffffffu, mx1, 1));
            mx1 = fmaxf(mx1, __shfl_xor_sync(0xffffffffu, mx1, 2));

            float mn0 = fmaxf(m0, mx0), mn1 = fmaxf(m1, mx1);
            float al0 = ex2f(m0 - mn0), al1 = ex2f(m1 - mn1);
            m0 = mn0; m1 = mn1;

            float s0 = 0.f, s1 = 0.f;
#pragma unroll
            for (int j = 0; j < 8; j++) {
                c[j][0] = ex2f(c[j][0] - mn0); s0 += c[j][0];
                c[j][1] = ex2f(c[j][1] - mn0); s0 += c[j][1];
                c[j][2] = ex2f(c[j][2] - mn1); s1 += c[j][2];
                c[j][3] = ex2f(c[j][3] - mn1); s1 += c[j][3];
            }
            s0 += __shfl_xor_sync(0xffffffffu, s0, 1);
            s0 += __shfl_xor_sync(0xffffffffu, s0, 2);
            s1 += __shfl_xor_sync(0xffffffffu, s1, 1);
            s1 += __shfl_xor_sync(0xffffffffu, s1, 2);
            l0 = l0 * al0 + s0;
            l1 = l1 * al1 + s1;

#pragma unroll
            for (int j = 0; j < 8; j++) {
                o[j][0] *= al0; o[j][1] *= al0;
                o[j][2] *= al1; o[j][3] *= al1;
            }

            // ---- O += P @ V ----
            {
                const unsigned vb = vbase0 + cur * 9216;
#pragma unroll
                for (int u = 0; u < 4; u++) {
                    unsigned pa[4];
                    pa[0] = f2h2(c[2 * u][0], c[2 * u][1]);
                    pa[1] = f2h2(c[2 * u][2], c[2 * u][3]);
                    pa[2] = f2h2(c[2 * u + 1][0], c[2 * u + 1][1]);
                    pa[3] = f2h2(c[2 * u + 1][2], c[2 * u + 1][3]);
#pragma unroll
                    for (int j2 = 0; j2 < 4; j2++) {
                        unsigned b0, b1, b2, b3;
                        ldsm4t(b0, b1, b2, b3, vb + u * 2304 + j2 * 32);
                        mma16816(o[2 * j2],     pa, b0, b1);
                        mma16816(o[2 * j2 + 1], pa, b2, b3);
                    }
                }
            }
        }

        float inv0 = 1.f / l0, inv1 = 1.f / l1;
        __half* outp = g_ao16 + (size_t)(qh * 64) * CDIM + head * 64;
#pragma unroll
        for (int j = 0; j < 8; j++) {
            int col = 8 * j + 2 * t;
            *(__half2*)&outp[(size_t)r0 * CDIM + col] =
                __floats2half2_rn(o[j][0] * inv0, o[j][1] * inv0);
            *(__half2*)&outp[(size_t)r1 * CDIM + col] =
                __floats2half2_rn(o[j][2] * inv1, o[j][3] * inv1);
        }
        __syncthreads();   // smem quiesced before next item's prologue
    }
}

// ---------------------------------------------------------------------------
extern "C" void kernel_launch(void* const* d_in, const int* in_sizes, int n_in,
                              void* d_out, int out_size) {
    const float* x      = (const float*)d_in[0];
    const float* qkv_w  = (const float*)d_in[1];
    const float* qkv_b  = (const float*)d_in[2];
    const float* proj_w = (const float*)d_in[3];
    const float* proj_b = (const float*)d_in[4];
    const float* rph    = (const float*)d_in[5];
    const float* rpw    = (const float*)d_in[6];
    float* out = (float*)d_out;

    const int GEMM_SMEM  = 36864 * 2;   // 73728 B
    const int FLASH_SMEM = 32256 * 2;   // 64512 B -> 3 CTAs/SM
    cudaFuncSetAttribute(qkv_hgemm16, cudaFuncAttributeMaxDynamicSharedMemorySize, GEMM_SMEM);
    cudaFuncSetAttribute(proj_hgemm16, cudaFuncAttributeMaxDynamicSharedMemorySize, GEMM_SMEM);
    cudaFuncSetAttribute(flash_attn, cudaFuncAttributeMaxDynamicSharedMemorySize, FLASH_SMEM);

    prep_kernel<<<5376, 256>>>(x, qkv_w, proj_w);
    qkv_hgemm16<<<dim3(18, 32), 256, GEMM_SMEM>>>(qkv_b);
    flash_attn<<<FLASH_GRID, 128, FLASH_SMEM>>>(rph, rpw);
    proj_hgemm16<<<dim3(6, 32), 256, GEMM_SMEM>>>(proj_b, out);
}

// round 17
// speedup vs baseline: 1.0639x; 1.0334x over previous
#include <cuda_runtime.h>
#include <cuda_fp16.h>

// SAM Vision Attention: B=1, H=W=64, N=4096, C=768, nh=12, hd=64
// R17: flash softmax -> ex2.approx.f16x2 (MUFU halved; exp output IS the
//      fp16 P fragment) and l accumulated via ones-column MMA (replaces the
//      FADD/SHFL sum reduction). Everything else = validated R16.

#define NH 12
#define NQ 4096
#define HD 64
#define CDIM 768
#define L2E 1.44269504f
#define SCALE_L2E (0.125f * 1.44269504f)   // 64^-0.5 * log2(e), folded into k

#define FLASH_ITEMS 768                    // (head, image-row) pairs
#define FLASH_GRID 456                     // 152 SMs x 3 CTAs
#define H2_ONES 0x3C003C00u                // (1.0h, 1.0h)

__device__ __half g_q16[NH * NQ * HD];
__device__ __half g_k16[NH * NQ * HD];        // pre-scaled by SCALE_L2E
__device__ __half g_v16[NH * NQ * HD];
__device__ __half g_ao16[NQ * CDIM];          // attention output (proj A input)
__device__ __half g_x16[NQ * CDIM];           // x in fp16
__device__ __half g_wqkvT[3 * CDIM * CDIM];   // qkv_w^T  [2304][768] fp16
__device__ __half g_wprojT[CDIM * CDIM];      // proj_w^T [768][768] fp16
__device__ int    g_counter;                  // flash work-stealing counter

// ---------------------------------------------------------------------------
// helpers
// ---------------------------------------------------------------------------
__device__ __forceinline__ void mma16816(float* c, const unsigned* a,
                                         unsigned b0, unsigned b1) {
    asm volatile(
        "mma.sync.aligned.m16n8k16.row.col.f32.f16.f16.f32 "
        "{%0,%1,%2,%3}, {%4,%5,%6,%7}, {%8,%9}, {%0,%1,%2,%3};\n"
        : "+f"(c[0]), "+f"(c[1]), "+f"(c[2]), "+f"(c[3])
        : "r"(a[0]), "r"(a[1]), "r"(a[2]), "r"(a[3]), "r"(b0), "r"(b1));
}

__device__ __forceinline__ unsigned f2h2(float x, float y) {
    __half2 h = __floats2half2_rn(x, y);
    return *(unsigned*)&h;
}

__device__ __forceinline__ float ex2f(float x) {
    float y;
    asm("ex2.approx.f32 %0, %1;" : "=f"(y) : "f"(x));
    return y;
}

__device__ __forceinline__ unsigned h2ex2(unsigned x) {
    unsigned y;
    asm("ex2.approx.f16x2 %0, %1;" : "=r"(y) : "r"(x));
    return y;
}

__device__ __forceinline__ void cp_async16(void* dst, const void* src) {
    unsigned d = (unsigned)__cvta_generic_to_shared(dst);
    asm volatile("cp.async.cg.shared.global [%0], [%1], 16;\n" :: "r"(d), "l"(src));
}
#define CP_COMMIT asm volatile("cp.async.commit_group;\n")
#define CP_WAIT(n) asm volatile("cp.async.wait_group %0;\n" :: "n"(n))

__device__ __forceinline__ void ldsm4(unsigned& r0, unsigned& r1, unsigned& r2,
                                      unsigned& r3, unsigned a) {
    asm volatile("ldmatrix.sync.aligned.m8n8.x4.shared.b16 {%0,%1,%2,%3}, [%4];"
                 : "=r"(r0), "=r"(r1), "=r"(r2), "=r"(r3) : "r"(a));
}
__device__ __forceinline__ void ldsm4t(unsigned& r0, unsigned& r1, unsigned& r2,
                                       unsigned& r3, unsigned a) {
    asm volatile("ldmatrix.sync.aligned.m8n8.x4.trans.shared.b16 {%0,%1,%2,%3}, [%4];"
                 : "=r"(r0), "=r"(r1), "=r"(r2), "=r"(r3) : "r"(a));
}

// ---------------------------------------------------------------------------
// fused prep kernel (validated R16)
// ---------------------------------------------------------------------------
__global__ void prep_kernel(const float* __restrict__ X,
                            const float* __restrict__ Wqkv,
                            const float* __restrict__ Wproj) {
    __shared__ float tile[32][33];
    const int bid = blockIdx.x;
    const int tid = threadIdx.x;
    if (bid == 0 && tid == 0) g_counter = 0;

    if (bid < 3072) {
        int i = bid * 256 + tid;
        float4 v = ((const float4*)X)[i];
        __half2* o = (__half2*)(g_x16 + (size_t)i * 4);
        o[0] = __floats2half2_rn(v.x, v.y);
        o[1] = __floats2half2_rn(v.z, v.w);
    } else if (bid < 4800) {
        int b = bid - 3072;
        int bn = (b % 72) * 32, bk = (b / 72) * 32;
        int tx = tid & 31, ty = tid >> 5;
#pragma unroll
        for (int i = 0; i < 32; i += 8)
            tile[ty + i][tx] = Wqkv[(size_t)(bk + ty + i) * 2304 + bn + tx];
        __syncthreads();
#pragma unroll
        for (int i = 0; i < 32; i += 8)
            g_wqkvT[(size_t)(bn + ty + i) * 768 + bk + tx] =
                __float2half(tile[tx][ty + i]);
    } else {
        int b = bid - 4800;
        int bn = (b % 24) * 32, bk = (b / 24) * 32;
        int tx = tid & 31, ty = tid >> 5;
#pragma unroll
        for (int i = 0; i < 32; i += 8)
            tile[ty + i][tx] = Wproj[(size_t)(bk + ty + i) * 768 + bn + tx];
        __syncthreads();
#pragma unroll
        for (int i = 0; i < 32; i += 8)
            g_wprojT[(size_t)(bn + ty + i) * 768 + bk + tx] =
                __float2half(tile[tx][ty + i]);
    }
}

// ---------------------------------------------------------------------------
// Shared fp16 HMMA GEMM body (validated R13)
// ---------------------------------------------------------------------------
struct GAcc { float c[2][8][4]; };

__device__ __forceinline__ void gemm_load_tile64(const __half* __restrict__ A,
                                                 const __half* __restrict__ BT,
                                                 int bm, int bn, int k0,
                                                 __half* dA, __half* dB, int tid) {
#pragma unroll
    for (int i = 0; i < 4; i++) {
        int cdx = tid + i * 256;
        int row = cdx >> 3, off = (cdx & 7) * 8;
        cp_async16(dA + row * 72 + off, A + (size_t)(bm + row) * 768 + k0 + off);
        cp_async16(dB + row * 72 + off, BT + (size_t)(bn + row) * 768 + k0 + off);
    }
    CP_COMMIT;
}

__device__ __forceinline__ void hgemm_body(const __half* __restrict__ A,
                                           const __half* __restrict__ BT,
                                           int bm, int bn, __half* As, __half* Bs,
                                           GAcc& F) {
    const int tid = threadIdx.x;
    const int w = tid >> 5, lane = tid & 31;
    const int m0 = (w >> 1) * 32, n0 = (w & 1) * 64;
    const int mat = lane >> 3, mr = lane & 7;

    const unsigned aconst = ((mat & 1) * 8 + mr) * 144 + (mat >> 1) * 16;
    const unsigned bconst = ((mat >> 1) * 8 + mr) * 144 + (mat & 1) * 16;
    const unsigned abase = (unsigned)__cvta_generic_to_shared(As) + m0 * 144 + aconst;
    const unsigned bbase = (unsigned)__cvta_generic_to_shared(Bs) + n0 * 144 + bconst;

#pragma unroll
    for (int mi = 0; mi < 2; mi++)
#pragma unroll
        for (int nj = 0; nj < 8; nj++)
#pragma unroll
            for (int e = 0; e < 4; e++) F.c[mi][nj][e] = 0.f;

    gemm_load_tile64(A, BT, bm, bn, 0, As, Bs, tid);

    for (int kt = 0; kt < 12; kt++) {
        const int cur = kt & 1;
        CP_WAIT(0);
        __syncthreads();

        if (kt < 11)
            gemm_load_tile64(A, BT, bm, bn, (kt + 1) * 64,
                             As + (cur ^ 1) * 9216, Bs + (cur ^ 1) * 9216, tid);

        const unsigned ab = abase + cur * 18432;
        const unsigned bb = bbase + cur * 18432;
#pragma unroll
        for (int ks = 0; ks < 4; ks++) {
            unsigned a[2][4], b[8][2];
#pragma unroll
            for (int mi = 0; mi < 2; mi++)
                ldsm4(a[mi][0], a[mi][1], a[mi][2], a[mi][3],
                      ab + mi * (16 * 144) + ks * 32);
#pragma unroll
            for (int nj2 = 0; nj2 < 4; nj2++)
                ldsm4(b[2 * nj2][0], b[2 * nj2][1], b[2 * nj2 + 1][0], b[2 * nj2 + 1][1],
                      bb + nj2 * (16 * 144) + ks * 32);
#pragma unroll
            for (int mi = 0; mi < 2; mi++)
#pragma unroll
                for (int nj = 0; nj < 8; nj++)
                    mma16816(F.c[mi][nj], a[mi], b[nj][0], b[nj][1]);
        }
    }
    __syncthreads();
}

// ---------------------------------------------------------------------------
// QKV GEMM: M=4096, N=2304 (validated R13)
// ---------------------------------------------------------------------------
__global__ __launch_bounds__(256, 2) void qkv_hgemm16(const float* __restrict__ bias) {
    extern __shared__ __half smq[];
    const int bm = blockIdx.y * 128, bn = blockIdx.x * 128;
    const int tid = threadIdx.x;
    const int w = tid >> 5, lane = tid & 31;
    const int g = lane >> 2, t = lane & 3;
    const int m0 = (w >> 1) * 32, n0 = (w & 1) * 64;

    GAcc F;
    hgemm_body(g_x16, g_wqkvT, bm, bn, smq, smq + 18432, F);

#pragma unroll
    for (int mi = 0; mi < 2; mi++)
#pragma unroll
        for (int nj = 0; nj < 8; nj++)
#pragma unroll
            for (int e2 = 0; e2 < 2; e2++) {
                int row = bm + m0 + mi * 16 + g + e2 * 8;
                int col = bn + n0 + nj * 8 + 2 * t;
                float v0 = F.c[mi][nj][e2 * 2 + 0] + bias[col];
                float v1 = F.c[mi][nj][e2 * 2 + 1] + bias[col + 1];
                int which = col / 768;
                int rem = col - which * 768;
                int head = rem >> 6, d = rem & 63;
                size_t off = ((size_t)head * NQ + row) * HD + d;
                if (which == 0)
                    *(__half2*)(g_q16 + off) = __floats2half2_rn(v0, v1);
                else if (which == 1)
                    *(__half2*)(g_k16 + off) =
                        __floats2half2_rn(v0 * SCALE_L2E, v1 * SCALE_L2E);
                else
                    *(__half2*)(g_v16 + off) = __floats2half2_rn(v0, v1);
            }
}

// ---------------------------------------------------------------------------
// proj GEMM: M=4096, N=768 (validated R13)
// ---------------------------------------------------------------------------
__global__ __launch_bounds__(256, 2) void proj_hgemm16(const float* __restrict__ bias,
                                                       float* __restrict__ out) {
    extern __shared__ __half smp[];
    const int bm = blockIdx.y * 128, bn = blockIdx.x * 128;
    const int tid = threadIdx.x;
    const int w = tid >> 5, lane = tid & 31;
    const int g = lane >> 2, t = lane & 3;
    const int m0 = (w >> 1) * 32, n0 = (w & 1) * 64;

    GAcc F;
    hgemm_body(g_ao16, g_wprojT, bm, bn, smp, smp + 18432, F);

#pragma unroll
    for (int mi = 0; mi < 2; mi++)
#pragma unroll
        for (int nj = 0; nj < 8; nj++)
#pragma unroll
            for (int e2 = 0; e2 < 2; e2++) {
                int row = bm + m0 + mi * 16 + g + e2 * 8;
                int col = bn + n0 + nj * 8 + 2 * t;
                float2 v;
                v.x = F.c[mi][nj][e2 * 2 + 0] + bias[col];
                v.y = F.c[mi][nj][e2 * 2 + 1] + bias[col + 1];
                *(float2*)&out[(size_t)row * 768 + col] = v;
            }
}

// ---------------------------------------------------------------------------
// Persistent flash attention: 456 CTAs (3/SM), stealing over 768 items.
// f16x2 exp softmax; l via ones-column MMA.
// smem (halves): Qs[0,4608) | K 2x[4608,13824) | V 2x[13824,23040)
//                RWs[23040,27648) | RHs[27648,32256)    = 64512 B
// ---------------------------------------------------------------------------
__global__ __launch_bounds__(128, 3) void flash_attn(const float* __restrict__ rph,
                                                     const float* __restrict__ rpw) {
    extern __shared__ __half smd[];
    __shared__ int s_item;
    __half* Qs  = smd;                 // [64][72]
    __half* Ksh = smd + 4608;          // 2 x [64][72]
    __half* Vsh = smd + 13824;         // 2 x [64][72]
    __half* RWs = smd + 23040;         // [64][72]  (xL2E)
    __half* RHs = smd + 27648;         // [64][72]  (xL2E)

    const int tid  = threadIdx.x;
    const int w    = tid >> 5;
    const int lane = tid & 31;
    const int g    = lane >> 2;
    const int t    = lane & 3;
    const int r0 = 16 * w + g;
    const int r1 = r0 + 8;

    const int mat = lane >> 3, mr = lane & 7;
    const unsigned smem_u32 = (unsigned)__cvta_generic_to_shared(smd);
    const unsigned kconst = ((mat >> 1) * 8 + mr) * 144 + (mat & 1) * 16;
    const unsigned vconst = ((mat & 1) * 8 + mr) * 144 + (mat >> 1) * 16;
    const unsigned kbase0 = smem_u32 + 4608 * 2 + kconst;
    const unsigned vbase0 = smem_u32 + 13824 * 2 + vconst;

    while (true) {
        if (tid == 0) s_item = atomicAdd(&g_counter, 1);
        __syncthreads();
        const int item = s_item;
        if (item >= FLASH_ITEMS) return;
        const int head = item >> 6;
        const int qh   = item & 63;

        const size_t qbase = ((size_t)head * NQ + qh * 64) * HD;
        const size_t hbase = (size_t)head * NQ * HD;

        // ---- prologue phase 1: load Q, Bh, Bw ----
        {
            __half* Bh = smd + 4608;
            __half* Bw = smd + 9216;
            const unsigned* gq = (const unsigned*)(g_q16 + qbase);
            for (int i = tid; i < 2048; i += 128) {
                int r = i >> 5, c2 = i & 31;
                *(unsigned*)&Qs[r * 72 + c2 * 2] = gq[i];
            }
            for (int i = tid; i < 4096; i += 128) {
                int kh = i >> 6, c = i & 63;
                Bh[kh * 72 + c] = __float2half(rph[(qh - kh + 63) * 64 + c]);
            }
            for (int i = tid; i < 127 * 64; i += 128) {
                int r = i >> 6, c = i & 63;
                Bw[r * 72 + c] = __float2half(rpw[i]);
            }
            if (tid < 64) Bw[127 * 72 + tid] = __float2half(0.f);
        }
        __syncthreads();

        // ---- Q fragments ----
        unsigned qa[4][4];
#pragma unroll
        for (int u = 0; u < 4; u++) {
            int d = 16 * u + 2 * t;
            qa[u][0] = *(const unsigned*)&Qs[r0 * 72 + d];
            qa[u][1] = *(const unsigned*)&Qs[r1 * 72 + d];
            qa[u][2] = *(const unsigned*)&Qs[r0 * 72 + d + 8];
            qa[u][3] = *(const unsigned*)&Qs[r1 * 72 + d + 8];
        }

        // ---- prologue phase 2: RH = Q @ Bh^T (xL2E) ----
        {
            float ch[8][4];
#pragma unroll
            for (int j = 0; j < 8; j++)
#pragma unroll
                for (int e = 0; e < 4; e++) ch[j][e] = 0.f;
            const unsigned bhb = smem_u32 + 4608 * 2 + kconst;
#pragma unroll
            for (int u = 0; u < 4; u++)
#pragma unroll
                for (int j2 = 0; j2 < 4; j2++) {
                    unsigned b0, b1, b2, b3;
                    ldsm4(b0, b1, b2, b3, bhb + j2 * 2304 + u * 32);
                    mma16816(ch[2 * j2],     qa[u], b0, b1);
                    mma16816(ch[2 * j2 + 1], qa[u], b2, b3);
                }
#pragma unroll
            for (int j = 0; j < 8; j++) {
                int col = 8 * j + 2 * t;
                *(unsigned*)&RHs[r0 * 72 + col] = f2h2(ch[j][0] * L2E, ch[j][1] * L2E);
                *(unsigned*)&RHs[r1 * 72 + col] = f2h2(ch[j][2] * L2E, ch[j][3] * L2E);
            }
        }

        // ---- prologue phase 3: P = Q @ Bw^T, gather RWs ----
        {
            float cp[16][4];
#pragma unroll
            for (int j = 0; j < 16; j++)
#pragma unroll
                for (int e = 0; e < 4; e++) cp[j][e] = 0.f;
            const unsigned bwb = smem_u32 + 9216 * 2 + kconst;
#pragma unroll
            for (int u = 0; u < 4; u++)
#pragma unroll
                for (int j2 = 0; j2 < 8; j2++) {
                    unsigned b0, b1, b2, b3;
                    ldsm4(b0, b1, b2, b3, bwb + j2 * 2304 + u * 32);
                    mma16816(cp[2 * j2],     qa[u], b0, b1);
                    mma16816(cp[2 * j2 + 1], qa[u], b2, b3);
                }
            __syncthreads();

            __half* Psm = smd + 4608;      // [64][136]
#pragma unroll
            for (int nj = 0; nj < 16; nj++) {
                int col = 8 * nj + 2 * t;
                *(unsigned*)&Psm[r0 * 136 + col] = f2h2(cp[nj][0] * L2E, cp[nj][1] * L2E);
                *(unsigned*)&Psm[r1 * 136 + col] = f2h2(cp[nj][2] * L2E, cp[nj][3] * L2E);
            }
            __syncthreads();

            for (int i = tid; i < 4096; i += 128) {
                int q = i >> 6, kw = i & 63;
                RWs[q * 72 + kw] = Psm[q * 136 + (q - kw + 63)];
            }
        }
        __syncthreads();

        // ---- prefetch key tile 0 ----
        {
            const __half* gk = g_k16 + hbase;
            const __half* gv = g_v16 + hbase;
#pragma unroll
            for (int i = 0; i < 4; i++) {
                int c = tid + i * 128;
                int key = c >> 3, off = (c & 7) * 8;
                cp_async16(&Ksh[key * 72 + off], gk + c * 8);
                cp_async16(&Vsh[key * 72 + off], gv + c * 8);
            }
            CP_COMMIT;
        }

        float o[8][4];
#pragma unroll
        for (int j = 0; j < 8; j++)
#pragma unroll
            for (int e = 0; e < 4; e++) o[j][e] = 0.f;
        float la[4] = {0.f, 0.f, 0.f, 0.f};      // l accumulator (ones-column MMA)
        float m0 = -1e30f, m1 = -1e30f;

        for (int kt = 0; kt < 64; kt++) {
            const int cur = kt & 1;
            CP_WAIT(0);
            __syncthreads();

            if (kt < 63) {
                const __half* gk = g_k16 + hbase + (size_t)(kt + 1) * 4096;
                const __half* gv = g_v16 + hbase + (size_t)(kt + 1) * 4096;
                __half* dk = Ksh + (cur ^ 1) * 4608;
                __half* dv = Vsh + (cur ^ 1) * 4608;
#pragma unroll
                for (int i = 0; i < 4; i++) {
                    int c = tid + i * 128;
                    int key = c >> 3, off = (c & 7) * 8;
                    cp_async16(&dk[key * 72 + off], gk + c * 8);
                    cp_async16(&dv[key * 72 + off], gv + c * 8);
                }
                CP_COMMIT;
            }

            // ---- S accumulators initialized with bias (rh + rw, xL2E) ----
            float c[8][4];
            {
                float rh0 = __half2float(RHs[r0 * 72 + kt]);
                float rh1 = __half2float(RHs[r1 * 72 + kt]);
#pragma unroll
                for (int j = 0; j < 8; j++) {
                    int col = 8 * j + 2 * t;
                    float2 w0 = __half22float2(*(const __half2*)&RWs[r0 * 72 + col]);
                    float2 w1 = __half22float2(*(const __half2*)&RWs[r1 * 72 + col]);
                    c[j][0] = rh0 + w0.x;
                    c[j][1] = rh0 + w0.y;
                    c[j][2] = rh1 + w1.x;
                    c[j][3] = rh1 + w1.y;
                }
            }

            // ---- S += Q @ K^T ----
            {
                const unsigned kb = kbase0 + cur * 9216;
#pragma unroll
                for (int u = 0; u < 4; u++) {
#pragma unroll
                    for (int j2 = 0; j2 < 4; j2++) {
                        unsigned b0, b1, b2, b3;
                        ldsm4(b0, b1, b2, b3, kb + j2 * 2304 + u * 32);
                        mma16816(c[2 * j2],     qa[u], b0, b1);
                        mma16816(c[2 * j2 + 1], qa[u], b2, b3);
                    }
                }
            }

            // ---- running max ----
            float mx0 = -1e30f, mx1 = -1e30f;
#pragma unroll
            for (int j = 0; j < 8; j++) {
                mx0 = fmaxf(mx0, fmaxf(c[j][0], c[j][1]));
                mx1 = fmaxf(mx1, fmaxf(c[j][2], c[j][3]));
            }
            mx0 = fmaxf(mx0, __shfl_xor_sync(0xffffffffu, mx0, 1));
            mx0 = fmaxf(mx0, __shfl_xor_sync(0xffffffffu, mx0, 2));
            mx1 = fmaxf(mx1, __shfl_xor_sync(0xffffffffu, mx1, 1));
            mx1 = fmaxf(mx1, __shfl_xor_sync(0xffffffffu, mx1, 2));

            float mn0 = fmaxf(m0, mx0), mn1 = fmaxf(m1, mx1);
            float al0 = ex2f(m0 - mn0), al1 = ex2f(m1 - mn1);
            m0 = mn0; m1 = mn1;

            // ---- P = exp2(S - m) directly in fp16x2 (P fragments) ----
            unsigned ph[8][2];
#pragma unroll
            for (int j = 0; j < 8; j++) {
                ph[j][0] = h2ex2(f2h2(c[j][0] - mn0, c[j][1] - mn0));
                ph[j][1] = h2ex2(f2h2(c[j][2] - mn1, c[j][3] - mn1));
            }

            // ---- rescale O and l ----
#pragma unroll
            for (int j = 0; j < 8; j++) {
                o[j][0] *= al0; o[j][1] *= al0;
                o[j][2] *= al1; o[j][3] *= al1;
            }
            la[0] *= al0; la[1] *= al0;
            la[2] *= al1; la[3] *= al1;

            // ---- O += P @ V ; l += P @ 1 ----
            {
                const unsigned vb = vbase0 + cur * 9216;
#pragma unroll
                for (int u = 0; u < 4; u++) {
                    unsigned pa[4];
                    pa[0] = ph[2 * u][0];
                    pa[1] = ph[2 * u][1];
                    pa[2] = ph[2 * u + 1][0];
                    pa[3] = ph[2 * u + 1][1];
                    mma16816(la, pa, H2_ONES, H2_ONES);
#pragma unroll
                    for (int j2 = 0; j2 < 4; j2++) {
                        unsigned b0, b1, b2, b3;
                        ldsm4t(b0, b1, b2, b3, vb + u * 2304 + j2 * 32);
                        mma16816(o[2 * j2],     pa, b0, b1);
                        mma16816(o[2 * j2 + 1], pa, b2, b3);
                    }
                }
            }
        }

        float inv0 = 1.f / la[0], inv1 = 1.f / la[2];
        __half* outp = g_ao16 + (size_t)(qh * 64) * CDIM + head * 64;
#pragma unroll
        for (int j = 0; j < 8; j++) {
            int col = 8 * j + 2 * t;
            *(__half2*)&outp[(size_t)r0 * CDIM + col] =
                __floats2half2_rn(o[j][0] * inv0, o[j][1] * inv0);
            *(__half2*)&outp[(size_t)r1 * CDIM + col] =
                __floats2half2_rn(o[j][2] * inv1, o[j][3] * inv1);
        }
        __syncthreads();   // smem quiesced before next item's prologue
    }
}

// ---------------------------------------------------------------------------
extern "C" void kernel_launch(void* const* d_in, const int* in_sizes, int n_in,
                              void* d_out, int out_size) {
    const float* x      = (const float*)d_in[0];
    const float* qkv_w  = (const float*)d_in[1];
    const float* qkv_b  = (const float*)d_in[2];
    const float* proj_w = (const float*)d_in[3];
    const float* proj_b = (const float*)d_in[4];
    const float* rph    = (const float*)d_in[5];
    const float* rpw    = (const float*)d_in[6];
    float* out = (float*)d_out;

    const int GEMM_SMEM  = 36864 * 2;   // 73728 B
    const int FLASH_SMEM = 32256 * 2;   // 64512 B -> 3 CTAs/SM
    cudaFuncSetAttribute(qkv_hgemm16, cudaFuncAttributeMaxDynamicSharedMemorySize, GEMM_SMEM);
    cudaFuncSetAttribute(proj_hgemm16, cudaFuncAttributeMaxDynamicSharedMemorySize, GEMM_SMEM);
    cudaFuncSetAttribute(flash_attn, cudaFuncAttributeMaxDynamicSharedMemorySize, FLASH_SMEM);

    prep_kernel<<<5376, 256>>>(x, qkv_w, proj_w);
    qkv_hgemm16<<<dim3(18, 32), 256, GEMM_SMEM>>>(qkv_b);
    flash_attn<<<FLASH_GRID, 128, FLASH_SMEM>>>(rph, rpw);
    proj_hgemm16<<<dim3(6, 32), 256, GEMM_SMEM>>>(proj_b, out);
}